// round 1
// baseline (speedup 1.0000x reference)
#include <cuda_runtime.h>

// Laplacian of sphere SDF over padded one-ring graph.
// inputs (metadata order):
//   d_in[0] verts_one_ring      [N,16,3] f32
//   d_in[1] verts_central_nodes [N,3]    f32
//   d_in[2] one_ring_mask       [N,16,1] f32
// output: concat(center_sdfs [N], lap [N]) -> 2N f32

__global__ void laplacian_sdf_kernel(const float* __restrict__ ring,
                                     const float* __restrict__ center,
                                     const float* __restrict__ mask,
                                     float* __restrict__ out,
                                     int N)
{
    long long gid = (long long)blockIdx.x * blockDim.x + threadIdx.x;
    long long node = gid >> 4;          // 16 lanes per node
    int k = (int)(gid & 15);
    if (node >= N) return;

    // ring vertex for this slot: contiguous 12B per lane -> coalesced
    const float* v = ring + node * 48 + k * 3;
    float dx = v[0] - 0.5f;
    float dy = v[1] - 0.5f;
    float dz = v[2] - 0.5f;
    float s = sqrtf(dx * dx + dy * dy + dz * dz) - 0.25f;

    float m = mask[node * 16 + k];
    float sm = s * m;

    // segmented reduction over the 16-lane group (groups are warp-aligned)
    #pragma unroll
    for (int off = 8; off > 0; off >>= 1) {
        sm += __shfl_xor_sync(0xffffffffu, sm, off);
        m  += __shfl_xor_sync(0xffffffffu, m,  off);
    }

    if (k == 0) {
        const float* c = center + node * 3;
        float cx = c[0] - 0.5f;
        float cy = c[1] - 0.5f;
        float cz = c[2] - 0.5f;
        float cs = sqrtf(cx * cx + cy * cy + cz * cz) - 0.25f;
        out[node]     = cs;
        out[N + node] = sm - m * cs;
    }
}

extern "C" void kernel_launch(void* const* d_in, const int* in_sizes, int n_in,
                              void* d_out, int out_size)
{
    const float* ring   = (const float*)d_in[0];
    const float* center = (const float*)d_in[1];
    const float* mask   = (const float*)d_in[2];
    float* out = (float*)d_out;

    int N = in_sizes[1] / 3;  // verts_central_nodes has N*3 elements

    long long total = (long long)N * 16;
    int threads = 256;
    long long blocks = (total + threads - 1) / threads;

    laplacian_sdf_kernel<<<(unsigned)blocks, threads>>>(ring, center, mask, out, N);
}

// round 2
// speedup vs baseline: 2.3513x; 2.3513x over previous
#include <cuda_runtime.h>

// Laplacian of sphere SDF over padded one-ring graph.
// inputs (metadata order):
//   d_in[0] verts_one_ring      [N,16,3] f32  (48 floats = 12 float4 per node)
//   d_in[1] verts_central_nodes [N,3]    f32
//   d_in[2] one_ring_mask       [N,16,1] f32  (16 floats = 4 float4 per node)
// output: concat(center_sdfs [N], lap [N]) -> 2N f32
//
// One lane per quarter-node (4 slots). All ring/mask traffic via LDG.128.

__device__ __forceinline__ float sdf3(float x, float y, float z)
{
    float dx = x - 0.5f, dy = y - 0.5f, dz = z - 0.5f;
    return sqrtf(fmaf(dx, dx, fmaf(dy, dy, dz * dz))) - 0.25f;
}

__global__ void laplacian_sdf_kernel(const float4* __restrict__ ring4,
                                     const float* __restrict__ center,
                                     const float4* __restrict__ mask4,
                                     float* __restrict__ out,
                                     int N)
{
    long long gid = (long long)blockIdx.x * blockDim.x + threadIdx.x;
    long long node = gid >> 2;          // 4 lanes per node
    int l = (int)(gid & 3);             // quarter index: slots 4l..4l+3
    if (node >= N) return;

    // 3 independent 16B loads + mask load: issue all up front
    const float4* r = ring4 + node * 12 + l * 3;
    float4 a = r[0];
    float4 b = r[1];
    float4 c = r[2];
    float4 mk = mask4[node * 4 + l];

    // 4 slots packed across a,b,c:
    //   s0=(a.x,a.y,a.z) s1=(a.w,b.x,b.y) s2=(b.z,b.w,c.x) s3=(c.y,c.z,c.w)
    float s0 = sdf3(a.x, a.y, a.z);
    float s1 = sdf3(a.w, b.x, b.y);
    float s2 = sdf3(b.z, b.w, c.x);
    float s3 = sdf3(c.y, c.z, c.w);

    float sm = fmaf(s0, mk.x, fmaf(s1, mk.y, fmaf(s2, mk.z, s3 * mk.w)));
    float m  = (mk.x + mk.y) + (mk.z + mk.w);

    // 2-level segmented reduction over the 4-lane group (lane-aligned)
    sm += __shfl_xor_sync(0xffffffffu, sm, 1);
    m  += __shfl_xor_sync(0xffffffffu, m,  1);
    sm += __shfl_xor_sync(0xffffffffu, sm, 2);
    m  += __shfl_xor_sync(0xffffffffu, m,  2);

    if (l == 0) {
        const float* cp = center + node * 3;
        float cs = sdf3(cp[0], cp[1], cp[2]);
        out[node]     = cs;
        out[N + node] = fmaf(-m, cs, sm);
    }
}

extern "C" void kernel_launch(void* const* d_in, const int* in_sizes, int n_in,
                              void* d_out, int out_size)
{
    const float4* ring4  = (const float4*)d_in[0];
    const float*  center = (const float*)d_in[1];
    const float4* mask4  = (const float4*)d_in[2];
    float* out = (float*)d_out;

    int N = in_sizes[1] / 3;  // verts_central_nodes has N*3 elements

    long long total = (long long)N * 4;
    int threads = 256;
    long long blocks = (total + threads - 1) / threads;

    laplacian_sdf_kernel<<<(unsigned)blocks, threads>>>(ring4, center, mask4, out, N);
}